// round 15
// baseline (speedup 1.0000x reference)
#include <cuda_runtime.h>
#include <cuda_bf16.h>

#define NATOMS 256
#define NMOL   4
#define NPAIRS 8192
#define NPHASE 2
#define NPSET  128
#define NBLK_PAIR (NPSET * NPHASE)     // 256
#define NBLK_BORN 32
#define NBLK1 (NBLK_PAIR + NBLK_BORN)  // 288
#define NBLK2 256
#define KEC      14.3996f
#define AA       0.3f
#define PI_F     3.14159265358979323846f
#define SQRTPI_F 1.7724538509055160273f
#define TWOPI_F  6.2831853071795864769f
#define INV2A      (1.0f/(2.0f*AA))
#define TWOA_SQPI  (2.0f*AA/SQRTPI_F)
#define FOURA_SQPI (4.0f*AA/SQRTPI_F)
#define INV_A_SQPI (1.0f/(AA*SQRTPI_F))

// j-side per-pair values, [phase][comp][j][i]; only read entries are rewritten
__device__ float  g_JM[NPHASE][9][NATOMS][NATOMS];
__device__ float  g_IP[NPHASE][NPSET][2][9];        // i-side partials
__device__ float  g_TIP[NPHASE][NPSET][2][NMOL*6];  // i-side T partials
__device__ float  g_Row[NATOMS][9];                 // row totals (k_red out)
__device__ float  g_TRow[NATOMS][NMOL*6];
__device__ float  g_Hb[NPAIRS][6];
// accumulators: zero at load; fin re-zeroes after consuming
__device__ float  g_Gb[NATOMS][3];
__device__ double g_Ec;
__device__ double g_Eb[NMOL];
__device__ int    g_cnt;

__device__ __forceinline__ float blockReduce256(float v, float* sh) {
    const unsigned full = 0xffffffffu;
    #pragma unroll
    for (int o = 16; o > 0; o >>= 1) v += __shfl_down_sync(full, v, o);
    int lane = threadIdx.x & 31, w = threadIdx.x >> 5;
    if (lane == 0) sh[w] = v;
    __syncthreads();
    float r = 0.f;
    if (w == 0) {
        r = (lane < 8) ? sh[lane] : 0.f;
        #pragma unroll
        for (int o = 4; o > 0; o >>= 1) r += __shfl_down_sync(full, r, o);
    }
    __syncthreads();
    return r;
}

// erfc(x)*exp(x*x), x>=0 (A&S 7.1.26)
__device__ __forceinline__ float erfcx_p(float x) {
    float t = __fdividef(1.f, fmaf(0.3275911f, x, 1.0f));
    float p = fmaf(t, 1.061405429f, -1.453152027f);
    p = fmaf(t, p, 1.421413741f);
    p = fmaf(t, p, -0.284496736f);
    p = fmaf(t, p, 0.254829592f);
    return t * p;
}

// ======================= kernel 1: triangle pair compute =======================
__global__ void __launch_bounds__(256) k_pair(const float* __restrict__ R,
                                              const float* __restrict__ shift,
                                              const float* __restrict__ q,
                                              const float* __restrict__ cell,
                                              const float* __restrict__ recip,
                                              const float* __restrict__ off,
                                              const float* __restrict__ r0_,
                                              const float* __restrict__ n_,
                                              const int* __restrict__ ii,
                                              const int* __restrict__ jj,
                                              const int* __restrict__ idxm,
                                              const int* __restrict__ isf) {
    __shared__ float  sRx[NATOMS], sRy[NATOMS], sRz[NATOMS], sq[NATOMS];
    __shared__ int    sfm[NATOMS], sml[NATOMS];
    __shared__ float4 sent[49];      // (k0,j1): u, w*exp(-u^2), 1/d, d
    __shared__ float  sax[25], say[25], saz[25];
    __shared__ float  red[32];
    __shared__ float  red2[8][9];
    __shared__ float  sTm[2][NMOL][6];
    __shared__ float  sE[NMOL];

    int t = threadIdx.x;
    int bid = blockIdx.x;

    float c0x = cell[0], c0y = cell[1], c0z = cell[2];
    float c1x = cell[3], c1y = cell[4], c1z = cell[5];
    float K0x = TWOPI_F * recip[0], K0y = TWOPI_F * recip[1], K0z = TWOPI_F * recip[2];
    float K1x = TWOPI_F * recip[3], K1y = TWOPI_F * recip[4], K1z = TWOPI_F * recip[5];
    float crx = c0y * c1z - c0z * c1y;
    float cry = c0z * c1x - c0x * c1z;
    float crz = c0x * c1y - c0y * c1x;
    float area = sqrtf(crx * crx + cry * cry + crz * crz);
    float PK = KEC * PI_F / area;
    bool axis = (K0y == 0.f) && (K0z == 0.f) && (K1x == 0.f) && (K1z == 0.f);

    {
        int m = idxm[t];
        float f = (isf[t] > 0) ? 1.f : 0.f;
        sRx[t] = R[t * 3 + 0] + f * shift[m * 3 + 0];
        sRy[t] = R[t * 3 + 1] + f * shift[m * 3 + 1];
        sRz[t] = R[t * 3 + 2] + f * shift[m * 3 + 2];
        sq[t]  = q[t];
        sml[t] = m;
        sfm[t] = (isf[t] > 0) ? m : -1;
    }
    if (t < 49) {
        int k0 = t / 7, j1 = t % 7;
        float fk = (float)k0, fj = (float)j1;
        float hx = fk * K0x + fj * K1x;
        float hy = fk * K0y + fj * K1y;
        float hz = fk * K0z + fj * K1z;
        float d2 = hx * hx + hy * hy + hz * hz;
        if (t == 0) d2 = 1.0f;                     // dummy (weight 0)
        float dd = sqrtf(d2);
        float uu = dd * INV2A;
        float w2 = (t == 0) ? 0.f : ((k0 == 0 || j1 == 0) ? 1.f : 2.f);
        sent[t] = make_float4(uu, w2 * __expf(-uu * uu), __fdividef(1.f, dd), dd);
    }
    if (t < 25) {
        float fn0 = (float)(t / 5 - 2), fn1 = (float)(t % 5 - 2);
        sax[t] = fn0 * c0x + fn1 * c1x;
        say[t] = fn0 * c0y + fn1 * c1y;
        saz[t] = fn0 * c0z + fn1 * c1z;
    }
    if (t < NMOL) sE[t] = 0.f;
    if (t < 2 * NMOL * 6) ((float*)sTm)[t] = 0.f;
    __syncthreads();

    if (bid < NBLK_PAIR) {
        // pairset b, phase ph; thread = one unordered pair (i < j)
        int b = bid & (NPSET - 1), ph = bid >> 7;
        int n1 = 255 - b;
        bool valid = (t < 255);
        int seg = (t < n1) ? 0 : 1;
        int i = 0, j = 1;
        if (t < n1)       { i = b;       j = b + 1 + t; }
        else if (t < 255) { i = 255 - b; j = i + 1 + (t - n1); }

        float E = 0.f;
        float vals[9];
        #pragma unroll
        for (int c = 0; c < 9; c++) vals[c] = 0.f;

        if (valid) {
            float dx = sRx[i] - sRx[j];
            float dy = sRy[i] - sRy[j];
            float dz = sRz[i] - sRz[j];
            float qq = sq[i] * sq[j];
            float az = AA * dz;
            float gzp = __expf(-az * az);
            float aaz = fabsf(az);

            float Ek = 0.f, Gkx = 0.f, Gky = 0.f, Gkz = 0.f;
            float Kxx = 0.f, Kyy = 0.f, Kzz = 0.f, Kxy = 0.f, Kxz = 0.f, Kyz = 0.f;
            float Er = 0.f, Grx = 0.f, Gry = 0.f, Grz = 0.f;
            float Rxx = 0.f, Ryy = 0.f, Rzz = 0.f, Rxy = 0.f, Rxz = 0.f, Ryz = 0.f;

            float alpha = K0x * dx + K0y * dy + K0z * dz;
            float beta  = K1x * dx + K1y * dy + K1z * dz;
            float sa, ca, sb, cb;
            sincosf(alpha, &sa, &ca);
            sincosf(beta,  &sb, &cb);

            int r0 = ph ? 4 : 0, r1 = ph ? 7 : 4;

            if (axis) {
                float cA, sA;
                if (ph == 0) { cA = 1.f; sA = 0.f; }
                else {
                    float c2a = ca * ca - sa * sa, s2a = 2.f * ca * sa;
                    cA = c2a * c2a - s2a * s2a;
                    sA = 2.f * c2a * s2a;
                }
                #pragma unroll 1
                for (int k0 = r0; k0 < r1; k0++) {
                    float Sec = 0.f, SesH = 0.f, SecH2 = 0.f;
                    float Sfc = 0.f, SfsH = 0.f, Sgc = 0.f;
                    float cB = 1.f, sB = 0.f;
                    const float4* row = &sent[k0 * 7];
                    #pragma unroll
                    for (int j1 = 0; j1 <= 6; j1++) {
                        float4 T = row[j1];
                        float x1 = T.x + az, x2 = T.x - az;
                        float gp = T.y * gzp;
                        float p1 = gp * erfcx_p(fabsf(x1));
                        float p2 = gp * erfcx_p(fabsf(x2));
                        if (aaz > T.x) {               // rare reflection
                            if (az > 0.f) p2 = 2.f * gp * __expf(x2 * x2) - p2;
                            else          p1 = 2.f * gp * __expf(x1 * x1) - p1;
                        }
                        float s   = p1 + p2;
                        float F   = s * T.z;           // carries orbit weight
                        float Fz  = p1 - p2;
                        float Fzz = fmaf(T.w, s, -FOURA_SQPI * gp);
                        float hy   = (float)j1 * K1y;
                        float Fhy  = F * hy;
                        float Fhy2 = Fhy * hy;
                        float Fzhy = Fz * hy;
                        Sec   = fmaf(cB, F,    Sec);
                        SesH  = fmaf(sB, Fhy,  SesH);
                        SecH2 = fmaf(cB, Fhy2, SecH2);
                        Sfc   = fmaf(cB, Fz,   Sfc);
                        SfsH  = fmaf(sB, Fzhy, SfsH);
                        Sgc   = fmaf(cB, Fzz,  Sgc);
                        float cBn = cB * cb - sB * sb;
                        sB = sB * cb + cB * sb;
                        cB = cBn;
                    }
                    float hx  = (float)k0 * K0x;
                    float hx2 = hx * hx;
                    float cSec = cA * Sec, sSec = sA * Sec;
                    Ek  += cSec;
                    Gkx = fmaf(-hx, sSec, Gkx);
                    Gky = fmaf(-cA, SesH, Gky);
                    Gkz = fmaf(cA, Sfc, Gkz);
                    Kxx = fmaf(-hx2, cSec, Kxx);
                    Kyy = fmaf(-cA, SecH2, Kyy);
                    Kxy = fmaf(hx, sA * SesH, Kxy);
                    Kxz = fmaf(-hx, sA * Sfc, Kxz);
                    Kyz = fmaf(-cA, SfsH, Kyz);
                    Kzz = fmaf(cA, Sgc, Kzz);
                    float cAn = cA * ca - sA * sa;
                    sA = sA * ca + cA * sa;
                    cA = cAn;
                }
            } else {
                // generic fallback (never hit on benchmark data)
                #pragma unroll 1
                for (int k0 = r0; k0 < r1; k0++) {
                    #pragma unroll 1
                    for (int j1 = (k0 == 0 ? 1 : -6); j1 <= 6; j1++) {
                        float fk = (float)k0, fj = (float)j1;
                        float hx = fk * K0x + fj * K1x;
                        float hy = fk * K0y + fj * K1y;
                        float hz = fk * K0z + fj * K1z;
                        float d2 = hx * hx + hy * hy + hz * hz;
                        float dd = sqrtf(d2);
                        float uu = dd * INV2A;
                        float gp = __expf(-uu * uu) * gzp;
                        float x1 = uu + az, x2 = uu - az;
                        float p1 = gp * erfcx_p(fabsf(x1));
                        float p2 = gp * erfcx_p(fabsf(x2));
                        if (aaz > uu) {
                            if (az > 0.f) p2 = 2.f * gp * __expf(x2 * x2) - p2;
                            else          p1 = 2.f * gp * __expf(x1 * x1) - p1;
                        }
                        float s   = p1 + p2;
                        float F   = s * __fdividef(1.f, dd);
                        float Fz  = p1 - p2;
                        float Fzz = fmaf(dd, s, -FOURA_SQPI * gp);
                        float ph2 = fk * alpha + fj * beta;
                        float sT2, cT;
                        sincosf(ph2, &sT2, &cT);
                        float cF = cT * F, sF = sT2 * F, sFz = sT2 * Fz;
                        Ek  += cF;
                        Gkx -= sF * hx;
                        Gky -= sF * hy;
                        Gkz += cT * Fz - sF * hz;
                        Kxx -= cF * hx * hx;
                        Kyy -= cF * hy * hy;
                        Kxy -= cF * hx * hy;
                        Kxz -= cF * hx * hz + sFz * hx;
                        Kyz -= cF * hy * hz + sFz * hy;
                        Kzz += cT * Fzz - cF * hz * hz - 2.f * sFz * hz;
                    }
                }
            }

            if (ph == 1) {
                float erfz = copysignf(1.f - erfcx_p(aaz) * gzp, az);
                Ek  -= dz * erfz + gzp * INV_A_SQPI;
                Gkz -= erfz;
                Kzz -= TWOA_SQPI * gzp;
            }
            int imS = ph ? 10 : 0, imE = ph ? 25 : 10;
            #pragma unroll 1
            for (int im = imS; im < imE; im++) {
                float rx = dx + sax[im];
                float ry = dy + say[im];
                float rz = dz + saz[im];
                float dd2 = rx * rx + ry * ry + rz * rz;
                if (dd2 > 0.f && dd2 < (81.0f / (AA * AA))) {
                    float invd  = rsqrtf(dd2);
                    float dr    = dd2 * invd;
                    float ad    = AA * dr;
                    float e     = __expf(-ad * ad);
                    float tt    = erfcx_p(ad) * e;
                    float invd2 = invd * invd;
                    Er += tt * invd;
                    float up  = -(TWOA_SQPI * e + tt * invd) * invd;
                    float upp = TWOA_SQPI * e * (2.f * AA * AA + 2.f * invd2) + 2.f * tt * invd * invd2;
                    float s1v = up * invd;
                    Grx += s1v * rx; Gry += s1v * ry; Grz += s1v * rz;
                    float w = (upp - s1v) * invd2;
                    Rxx += w * rx * rx + s1v;
                    Ryy += w * ry * ry + s1v;
                    Rzz += w * rz * rz + s1v;
                    Rxy += w * rx * ry;
                    Rxz += w * rx * rz;
                    Ryz += w * ry * rz;
                }
            }

            float pk = qq * PK;
            float p3 = qq * (0.5f * KEC);
            E = 2.f * (pk * Ek + p3 * Er);   // unordered pair: both orders
            vals[0] = pk * Gkx + p3 * Grx;
            vals[1] = pk * Gky + p3 * Gry;
            vals[2] = pk * Gkz + p3 * Grz;
            vals[3] = pk * Kxx + p3 * Rxx;
            vals[4] = pk * Kyy + p3 * Ryy;
            vals[5] = pk * Kzz + p3 * Rzz;
            vals[6] = pk * Kxy + p3 * Rxy;
            vals[7] = pk * Kxz + p3 * Rxz;
            vals[8] = pk * Kyz + p3 * Ryz;

            // j-side store (each j distinct within block)
            #pragma unroll
            for (int c = 0; c < 9; c++) g_JM[ph][c][j][i] = vals[c];

            // i-side T (film mol of j), segmented smem atomics
            int fmj = sfm[j];
            if (fmj >= 0) {
                #pragma unroll
                for (int c = 0; c < 6; c++)
                    atomicAdd(&sTm[seg][fmj][c], vals[3 + c]);
            }
        }

        // i-side segmented reductions (2 segments x 9 comps)
        const unsigned full = 0xffffffffu;
        #pragma unroll
        for (int s = 0; s < 2; s++) {
            #pragma unroll
            for (int c = 0; c < 9; c++) {
                float v = (valid && seg == s) ? vals[c] : 0.f;
                #pragma unroll
                for (int o = 16; o > 0; o >>= 1) v += __shfl_down_sync(full, v, o);
                if ((t & 31) == 0) red2[t >> 5][c] = v;
            }
            __syncthreads();
            if (t < 9) {
                float sum = 0.f;
                #pragma unroll
                for (int w = 0; w < 8; w++) sum += red2[w][t];
                g_IP[ph][b][s][t] = sum;
            }
            __syncthreads();
        }
        float se = blockReduce256(E, red);   // syncs publish sTm
        if (t == 0) atomicAdd(&g_Ec, (double)se);
        if (t < 2 * NMOL * 6) g_TIP[ph][b][t / 24][t % 24] = ((float*)sTm)[t];
    } else {
        // ---- born pairs ----
        int p = (bid - NBLK_PAIR) * 256 + t;
        int i = ii[p], j = jj[p];
        float rx = sRx[j] - sRx[i] + off[p * 3 + 0];
        float ry = sRy[j] - sRy[i] + off[p * 3 + 1];
        float rz = sRz[j] - sRz[i] + off[p * 3 + 2];
        float d2 = rx * rx + ry * ry + rz * rz;
        float d  = sqrtf(d2);
        float H[6] = {0.f, 0.f, 0.f, 0.f, 0.f, 0.f};

        if (d < 6.0f) {
            float n  = n_[p], r0v = r0_[p];
            float qq = fabsf(sq[i] * sq[j]);
            float B  = qq * __powf(r0v, n - 1.f) * __fdividef(1.f, n);
            float dn = __powf(d, -n);
            float cn = __powf(6.0f, -n);
            float y  = B * (dn - cn);
            atomicAdd(&sE[sml[i]], 0.5f * KEC * y);
            float f     = 0.5f * KEC;
            float invd  = __fdividef(1.f, d);
            float invd2 = invd * invd;
            float yp  = -n * B * dn * invd;
            float ypp = n * (n + 1.f) * B * dn * invd2;
            float s1  = f * yp * invd;
            atomicAdd(&g_Gb[j][0],  s1 * rx);
            atomicAdd(&g_Gb[j][1],  s1 * ry);
            atomicAdd(&g_Gb[j][2],  s1 * rz);
            atomicAdd(&g_Gb[i][0], -s1 * rx);
            atomicAdd(&g_Gb[i][1], -s1 * ry);
            atomicAdd(&g_Gb[i][2], -s1 * rz);
            float w = (f * ypp - s1) * invd2;
            H[0] = w * rx * rx + s1; H[1] = w * ry * ry + s1; H[2] = w * rz * rz + s1;
            H[3] = w * rx * ry; H[4] = w * rx * rz; H[5] = w * ry * rz;
        }
        #pragma unroll
        for (int c = 0; c < 6; c++) g_Hb[p][c] = H[c];
        __syncthreads();
        if (t < NMOL) atomicAdd(&g_Eb[t], (double)sE[t]);
    }
}

// ======================= kernel 2: row assemble + fin =======================
__global__ void __launch_bounds__(256) k_red(const float* __restrict__ q,
                                             const float* __restrict__ cell,
                                             const float* __restrict__ recip,
                                             const int* __restrict__ ii,
                                             const int* __restrict__ jj,
                                             const int* __restrict__ idxm,
                                             const int* __restrict__ isf,
                                             float* __restrict__ out) {
    __shared__ float red[32];
    __shared__ float red2[8][12];
    __shared__ float sTm[NMOL][6];
    __shared__ float sff[NMOL * 3];
    __shared__ float sv[NATOMS][3];
    __shared__ int   sfm[NATOMS];
    __shared__ int   sLast;

    int a = blockIdx.x, t = threadIdx.x;
    sfm[t] = (isf[t] > 0) ? idxm[t] : -1;
    if (t < NMOL * 6) ((float*)sTm)[t] = 0.f;
    __syncthreads();

    // column sums: pairs (i=t, a) for t < a  (j-side of stored values)
    bool has = (t < a);
    float vals[9];
    #pragma unroll
    for (int c = 0; c < 9; c++)
        vals[c] = has ? (g_JM[0][c][a][t] + g_JM[1][c][a][t]) : 0.f;

    if (has) {
        int mi = sfm[t];
        if (mi >= 0) {
            #pragma unroll
            for (int c = 0; c < 6; c++)
                atomicAdd(&sTm[mi][c], vals[3 + c]);
        }
    }

    const unsigned full = 0xffffffffu;
    #pragma unroll
    for (int c = 0; c < 9; c++) {
        float v = vals[c];
        #pragma unroll
        for (int o = 16; o > 0; o >>= 1) v += __shfl_down_sync(full, v, o);
        if ((t & 31) == 0) red2[t >> 5][c] = v;
    }
    __syncthreads();
    if (t < 9) {
        float col = 0.f;
        #pragma unroll
        for (int w = 0; w < 8; w++) col += red2[w][t];
        // i-side partials for row a
        int b = (a < NPSET) ? a : (255 - a);
        int slot = (a < NPSET) ? 0 : 1;
        float ip = g_IP[0][b][slot][t] + g_IP[1][b][slot][t];
        // G (comps 0-2): i-side +, j-side -; H (3-8): both +
        g_Row[a][t] = (t < 3) ? (ip - col) : (ip + col);
    }
    if (t < NMOL * 6) {
        int b = (a < NPSET) ? a : (255 - a);
        int slot = (a < NPSET) ? 0 : 1;
        g_TRow[a][t] = g_TIP[0][b][slot][t] + g_TIP[1][b][slot][t] + ((float*)sTm)[t];
    }

    // ---- completion: last block finalizes ----
    __syncthreads();
    if (t == 0) {
        __threadfence();
        int old = atomicAdd(&g_cnt, 1);
        sLast = (old == NBLK2 - 1) ? 1 : 0;
    }
    __syncthreads();
    if (!sLast) return;
    __threadfence();

    float K0x = TWOPI_F * recip[0], K0y = TWOPI_F * recip[1], K0z = TWOPI_F * recip[2];
    float K1x = TWOPI_F * recip[3], K1y = TWOPI_F * recip[4], K1z = TWOPI_F * recip[5];
    float c0x = cell[0], c0y = cell[1], c0z = cell[2];
    float c1x = cell[3], c1y = cell[4], c1z = cell[5];
    float crx = c0y * c1z - c0z * c1y;
    float cry = c0z * c1x - c0x * c1z;
    float crz = c0x * c1y - c0y * c1x;
    float area = sqrtf(crx * crx + cry * cry + crz * crz);
    float PK = KEC * PI_F / area;

    int a2 = t;
    if (a2 < NMOL * 3) sff[a2] = 0.f;
    __syncthreads();

    float P[9];
    #pragma unroll
    for (int c = 0; c < 9; c++) P[c] = g_Row[a2][c];

    float Gx = 8.f * P[0] + g_Gb[a2][0];
    float Gy = 8.f * P[1] + g_Gb[a2][1];
    float Gz = 8.f * P[2] + g_Gb[a2][2];
    g_Gb[a2][0] = 0.f; g_Gb[a2][1] = 0.f; g_Gb[a2][2] = 0.f;
    int m = sfm[a2];
    bool film = (m >= 0);
    if (film) {
        atomicAdd(&sff[m * 3 + 0], -Gx);
        atomicAdd(&sff[m * 3 + 1], -Gy);
        atomicAdd(&sff[m * 3 + 2], -Gz);
    }
    // diag k-sum over the half-space: F_k(0) = 2*erfc(u)/|h|
    float Ed = 0.f;
    if (a2 < 84) {
        int k0, j1, sg;
        if (a2 < 6) { k0 = 0; j1 = a2 + 1; sg = 1; }
        else {
            int u2 = a2 - 6;
            k0 = 1 + u2 / 13;
            int r2 = u2 % 13;
            if (r2 == 0) { j1 = 0; sg = 1; }
            else { j1 = (r2 + 1) >> 1; sg = (r2 & 1) ? 1 : -1; }
        }
        float fj = (float)(sg * j1), fk = (float)k0;
        float hx = fk * K0x + fj * K1x;
        float hy = fk * K0y + fj * K1y;
        float hz = fk * K0z + fj * K1z;
        float dd = sqrtf(hx * hx + hy * hy + hz * hz);
        float uu = dd * INV2A;
        Ed = 2.f * erfcx_p(uu) * __expf(-uu * uu) * __fdividef(1.f, dd);
    }
    float qa = q[a2];
    float sq2 = blockReduce256(qa * qa, red);
    float sEd = blockReduce256(Ed, red);

    float vx = film ? sff[m * 3 + 0] : 0.f;
    float vy = film ? sff[m * 3 + 1] : 0.f;
    float vz = film ? sff[m * 3 + 2] : 0.f;
    sv[a2][0] = vx; sv[a2][1] = vy; sv[a2][2] = vz;

    float Hvx = P[3] * vx + P[6] * vy + P[7] * vz;
    float Hvy = P[6] * vx + P[4] * vy + P[8] * vz;
    float Hvz = P[7] * vx + P[8] * vy + P[5] * vz;
    #pragma unroll
    for (int m2 = 0; m2 < NMOL; m2++) {
        float T0 = g_TRow[a2][m2 * 6 + 0];
        float T1 = g_TRow[a2][m2 * 6 + 1];
        float T2 = g_TRow[a2][m2 * 6 + 2];
        float T3 = g_TRow[a2][m2 * 6 + 3];
        float T4 = g_TRow[a2][m2 * 6 + 4];
        float T5 = g_TRow[a2][m2 * 6 + 5];
        float fx = sff[m2 * 3 + 0], fy = sff[m2 * 3 + 1], fz = sff[m2 * 3 + 2];
        Hvx -= T0 * fx + T3 * fy + T4 * fz;
        Hvy -= T3 * fx + T1 * fy + T5 * fz;
        Hvz -= T4 * fx + T5 * fy + T2 * fz;
    }
    Hvx *= 8.f; Hvy *= 8.f; Hvz *= 8.f;

    float fax[4], fay[4], faz[4];
    #pragma unroll
    for (int k = 0; k < 4; k++) {
        bool me = film && (m == k);
        fax[k] = me ? Hvx : 0.f;
        fay[k] = me ? Hvy : 0.f;
        faz[k] = me ? Hvz : 0.f;
    }
    __syncthreads();

    #pragma unroll 1
    for (int p = a2; p < NPAIRS; p += 256) {
        int i2 = ii[p], j2 = jj[p];
        float h0 = g_Hb[p][0], h1 = g_Hb[p][1], h2 = g_Hb[p][2];
        float h3 = g_Hb[p][3], h4 = g_Hb[p][4], h5 = g_Hb[p][5];
        float dvx = sv[j2][0] - sv[i2][0];
        float dvy = sv[j2][1] - sv[i2][1];
        float dvz = sv[j2][2] - sv[i2][2];
        float wx = h0 * dvx + h3 * dvy + h4 * dvz;
        float wy = h3 * dvx + h1 * dvy + h5 * dvz;
        float wz = h4 * dvx + h5 * dvy + h2 * dvz;
        int mj = sfm[j2], mi = sfm[i2];
        #pragma unroll
        for (int k = 0; k < 4; k++) {
            float s = ((mj == k) ? 1.f : 0.f) - ((mi == k) ? 1.f : 0.f);
            fax[k] = fmaf(s, wx, fax[k]);
            fay[k] = fmaf(s, wy, fay[k]);
            faz[k] = fmaf(s, wz, faz[k]);
        }
    }

    const unsigned full2 = 0xffffffffu;
    #pragma unroll
    for (int k = 0; k < 4; k++) {
        float v0 = fax[k], v1 = fay[k], v2 = faz[k];
        #pragma unroll
        for (int o = 16; o > 0; o >>= 1) {
            v0 += __shfl_down_sync(full2, v0, o);
            v1 += __shfl_down_sync(full2, v1, o);
            v2 += __shfl_down_sync(full2, v2, o);
        }
        if ((t & 31) == 0) {
            red2[t >> 5][k * 3 + 0] = v0;
            red2[t >> 5][k * 3 + 1] = v1;
            red2[t >> 5][k * 3 + 2] = v2;
        }
    }
    __syncthreads();
    if (t < 12) {
        float s = 0.f;
        #pragma unroll
        for (int w = 0; w < 8; w++) s += red2[w][t];
        out[13 + t] = -2.f * s;
    }

    if (t == 0) {
        float yc = (float)g_Ec
                 + sq2 * (PK * (sEd - INV_A_SQPI) - (AA / SQRTPI_F) * KEC);
        out[4] = yc;
        #pragma unroll
        for (int m2 = 0; m2 < NMOL; m2++) {
            float yb = (float)g_Eb[m2];
            out[m2]     = yc + yb;
            out[5 + m2] = yb;
            float fx = sff[m2 * 3 + 0], fy = sff[m2 * 3 + 1], fz = sff[m2 * 3 + 2];
            out[9 + m2] = fx * fx + fy * fy + fz * fz;
        }
        g_Ec = 0.0;
        g_cnt = 0;
    }
    if (t < NMOL) g_Eb[t] = 0.0;
}

extern "C" void kernel_launch(void* const* d_in, const int* in_sizes, int n_in,
                              void* d_out, int out_size) {
    const float* R      = (const float*)d_in[0];
    const float* shift  = (const float*)d_in[1];
    const float* q      = (const float*)d_in[2];
    const float* off    = (const float*)d_in[3];
    const float* cell   = (const float*)d_in[4];
    const float* recip  = (const float*)d_in[5];
    const float* r0_ij  = (const float*)d_in[6];
    const float* n_ij   = (const float*)d_in[7];
    const int*   idx_i  = (const int*)d_in[8];
    const int*   idx_j  = (const int*)d_in[9];
    const int*   idx_m  = (const int*)d_in[10];
    const int*   isf    = (const int*)d_in[11];
    float* out = (float*)d_out;

    k_pair<<<NBLK1, 256>>>(R, shift, q, cell, recip, off, r0_ij, n_ij,
                           idx_i, idx_j, idx_m, isf);
    k_red<<<NBLK2, 256>>>(q, cell, recip, idx_i, idx_j, idx_m, isf, out);
}

// round 16
// speedup vs baseline: 1.2179x; 1.2179x over previous
#include <cuda_runtime.h>
#include <cuda_bf16.h>

#define NATOMS 256
#define NMOL   4
#define NPAIRS 8192
#define NPHASE 2
#define NBLK_PAIR (NATOMS * NPHASE)    // 512: row a = bid&255, phase = bid>>8
#define NBLK_BORN 32
#define NBLK (NBLK_PAIR + NBLK_BORN)   // 544
#define NIMG 9                          // n0,n1 in {-1,0,1}; |n|=2 images < 4e-17
#define KEC      14.3996f
#define AA       0.3f
#define PI_F     3.14159265358979323846f
#define SQRTPI_F 1.7724538509055160273f
#define TWOPI_F  6.2831853071795864769f
#define INV2A      (1.0f/(2.0f*AA))
#define TWOA_SQPI  (2.0f*AA/SQRTPI_F)
#define FOURA_SQPI (4.0f*AA/SQRTPI_F)
#define INV_A_SQPI (1.0f/(AA*SQRTPI_F))

// per-row-phase partials: plain stores, rewritten every call
__device__ float  g_RP[NPHASE][NATOMS][9];        // Gx,Gy,Gz,U0..U5 row partials
__device__ float  g_TP[NPHASE][NATOMS][NMOL*6];   // T row partials
__device__ float  g_Hb[NPAIRS][6];
// accumulators: zero at load; fin re-zeroes after consuming
__device__ float  g_Gb[NATOMS][3];
__device__ double g_Ec;
__device__ double g_Eb[NMOL];
__device__ int    g_cnt;

__device__ __forceinline__ float blockReduce256(float v, float* sh) {
    const unsigned full = 0xffffffffu;
    #pragma unroll
    for (int o = 16; o > 0; o >>= 1) v += __shfl_down_sync(full, v, o);
    int lane = threadIdx.x & 31, w = threadIdx.x >> 5;
    if (lane == 0) sh[w] = v;
    __syncthreads();
    float r = 0.f;
    if (w == 0) {
        r = (lane < 8) ? sh[lane] : 0.f;
        #pragma unroll
        for (int o = 4; o > 0; o >>= 1) r += __shfl_down_sync(full, r, o);
    }
    __syncthreads();
    return r;
}

// ---- packed f32x2 helpers (Blackwell) ----
__device__ __forceinline__ unsigned long long pk2(float a, float b) {
    unsigned long long r;
    asm("mov.b64 %0, {%1, %2};" : "=l"(r) : "f"(a), "f"(b));
    return r;
}
__device__ __forceinline__ void up2(unsigned long long v, float& a, float& b) {
    asm("mov.b64 {%0, %1}, %2;" : "=f"(a), "=f"(b) : "l"(v));
}
__device__ __forceinline__ unsigned long long fma2(unsigned long long a,
                                                   unsigned long long b,
                                                   unsigned long long c) {
    unsigned long long r;
    asm("fma.rn.f32x2 %0, %1, %2, %3;" : "=l"(r) : "l"(a), "l"(b), "l"(c));
    return r;
}
__device__ __forceinline__ unsigned long long mul2(unsigned long long a,
                                                   unsigned long long b) {
    unsigned long long r;
    asm("mul.rn.f32x2 %0, %1, %2;" : "=l"(r) : "l"(a), "l"(b));
    return r;
}

// erfc(x)*exp(x*x), x>=0 (A&S 7.1.26) — scalar version
__device__ __forceinline__ float erfcx_p(float x) {
    float t = __fdividef(1.f, fmaf(0.3275911f, x, 1.0f));
    float p = fmaf(t, 1.061405429f, -1.453152027f);
    p = fmaf(t, p, 1.421413741f);
    p = fmaf(t, p, -0.284496736f);
    p = fmaf(t, p, 0.254829592f);
    return t * p;
}

// p1 = gp*erfcx(|x1|), p2 = gp*erfcx(|x2|), packed poly
__device__ __forceinline__ void erfcx2(float x1, float x2, float gp,
                                       float& p1, float& p2) {
    float t1 = __fdividef(1.f, fmaf(0.3275911f, fabsf(x1), 1.0f));
    float t2 = __fdividef(1.f, fmaf(0.3275911f, fabsf(x2), 1.0f));
    unsigned long long T = pk2(t1, t2);
    unsigned long long p = fma2(T, pk2(1.061405429f, 1.061405429f),
                                   pk2(-1.453152027f, -1.453152027f));
    p = fma2(T, p, pk2(1.421413741f, 1.421413741f));
    p = fma2(T, p, pk2(-0.284496736f, -0.284496736f));
    p = fma2(T, p, pk2(0.254829592f, 0.254829592f));
    p = mul2(p, T);
    p = mul2(p, pk2(gp, gp));
    up2(p, p1, p2);
}

__global__ void __launch_bounds__(256) k_all(const float* __restrict__ R,
                                             const float* __restrict__ shift,
                                             const float* __restrict__ q,
                                             const float* __restrict__ cell,
                                             const float* __restrict__ recip,
                                             const float* __restrict__ off,
                                             const float* __restrict__ r0_,
                                             const float* __restrict__ n_,
                                             const int* __restrict__ ii,
                                             const int* __restrict__ jj,
                                             const int* __restrict__ idxm,
                                             const int* __restrict__ isf,
                                             float* __restrict__ out) {
    __shared__ float  sRx[NATOMS], sRy[NATOMS], sRz[NATOMS], sq[NATOMS];
    __shared__ int    sfm[NATOMS], sml[NATOMS];
    __shared__ float4 sent[49];      // (k0,j1): u, w*exp(-u^2), 1/d, d
    __shared__ float  sax[NIMG], say[NIMG], saz[NIMG];
    __shared__ float  red[32];
    __shared__ float  red2[8][12];
    __shared__ float  sTm[NMOL][6];
    __shared__ float  sE[NMOL];
    __shared__ float  sff[NMOL * 3];
    __shared__ float  sv[NATOMS][3];
    __shared__ int    sLast;

    int t = threadIdx.x;
    int bid = blockIdx.x;

    // ---- per-block preamble ----
    float c0x = cell[0], c0y = cell[1], c0z = cell[2];
    float c1x = cell[3], c1y = cell[4], c1z = cell[5];
    float K0x = TWOPI_F * recip[0], K0y = TWOPI_F * recip[1], K0z = TWOPI_F * recip[2];
    float K1x = TWOPI_F * recip[3], K1y = TWOPI_F * recip[4], K1z = TWOPI_F * recip[5];
    float crx = c0y * c1z - c0z * c1y;
    float cry = c0z * c1x - c0x * c1z;
    float crz = c0x * c1y - c0y * c1x;
    float area = sqrtf(crx * crx + cry * cry + crz * crz);
    float PK = KEC * PI_F / area;
    bool axis = (K0y == 0.f) && (K0z == 0.f) && (K1x == 0.f) && (K1z == 0.f);

    {
        int m = idxm[t];
        float f = (isf[t] > 0) ? 1.f : 0.f;
        sRx[t] = R[t * 3 + 0] + f * shift[m * 3 + 0];
        sRy[t] = R[t * 3 + 1] + f * shift[m * 3 + 1];
        sRz[t] = R[t * 3 + 2] + f * shift[m * 3 + 2];
        sq[t]  = q[t];
        sml[t] = m;
        sfm[t] = (isf[t] > 0) ? m : -1;
    }
    if (t < 49) {
        int k0 = t / 7, j1 = t % 7;
        float fk = (float)k0, fj = (float)j1;
        float hx = fk * K0x + fj * K1x;
        float hy = fk * K0y + fj * K1y;
        float hz = fk * K0z + fj * K1z;
        float d2 = hx * hx + hy * hy + hz * hz;
        if (t == 0) d2 = 1.0f;                     // dummy (weight 0)
        float dd = sqrtf(d2);
        float uu = dd * INV2A;
        float w2 = (t == 0) ? 0.f : ((k0 == 0 || j1 == 0) ? 1.f : 2.f);
        sent[t] = make_float4(uu, w2 * __expf(-uu * uu), __fdividef(1.f, dd), dd);
    }
    if (t < NIMG) {
        float fn0 = (float)(t / 3 - 1), fn1 = (float)(t % 3 - 1);
        sax[t] = fn0 * c0x + fn1 * c1x;
        say[t] = fn0 * c0y + fn1 * c1y;
        saz[t] = fn0 * c0z + fn1 * c1z;
    }
    if (t < NMOL) sE[t] = 0.f;
    if (t < NMOL * 6) ((float*)sTm)[t] = 0.f;
    __syncthreads();

    if (bid < NBLK_PAIR) {
        // ---- coulomb: row a, phase ph; thread = col j (full matrix incl diag)
        int a = bid & (NATOMS - 1), ph = bid >> 8;
        int j = t;
        float dx = sRx[a] - sRx[j];
        float dy = sRy[a] - sRy[j];
        float dz = sRz[a] - sRz[j];
        float qq = sq[a] * sq[j];
        float az = AA * dz;
        float gzp = __expf(-az * az);
        float aaz = fabsf(az);

        float Ek = 0.f, Gkx = 0.f, Gky = 0.f, Gkz = 0.f;
        float Kxx = 0.f, Kyy = 0.f, Kzz = 0.f, Kxy = 0.f, Kxz = 0.f, Kyz = 0.f;
        float Er = 0.f, Grx = 0.f, Gry = 0.f, Grz = 0.f;
        float Rxx = 0.f, Ryy = 0.f, Rzz = 0.f, Rxy = 0.f, Rxz = 0.f, Ryz = 0.f;

        float alpha = K0x * dx + K0y * dy + K0z * dz;
        float beta  = K1x * dx + K1y * dy + K1z * dz;
        float sa, ca, sb, cb;
        sincosf(alpha, &sa, &ca);
        sincosf(beta,  &sb, &cb);

        int r0 = ph ? 4 : 0, r1 = ph ? 7 : 4;

        if (axis) {
            float cA, sA;
            if (ph == 0) { cA = 1.f; sA = 0.f; }
            else {
                float c2a = ca * ca - sa * sa, s2a = 2.f * ca * sa;
                cA = c2a * c2a - s2a * s2a;        // cos 4a
                sA = 2.f * c2a * s2a;              // sin 4a
            }
            #pragma unroll 1
            for (int k0 = r0; k0 < r1; k0++) {
                float Sec = 0.f, SesH = 0.f, SecH2 = 0.f;
                float Sfc = 0.f, SfsH = 0.f, Sgc = 0.f;
                float cB = 1.f, sB = 0.f;
                const float4* row = &sent[k0 * 7];
                #pragma unroll
                for (int j1 = 0; j1 <= 6; j1++) {
                    float4 T = row[j1];
                    float x1 = T.x + az, x2 = T.x - az;
                    float gp = T.y * gzp;
                    float p1, p2;
                    erfcx2(x1, x2, gp, p1, p2);
                    if (aaz > T.x) {               // rare reflection
                        if (az > 0.f) p2 = 2.f * gp * __expf(x2 * x2) - p2;
                        else          p1 = 2.f * gp * __expf(x1 * x1) - p1;
                    }
                    float s   = p1 + p2;
                    float F   = s * T.z;           // carries orbit weight
                    float Fz  = p1 - p2;
                    float Fzz = fmaf(T.w, s, -FOURA_SQPI * gp);
                    float hy   = (float)j1 * K1y;
                    float Fhy  = F * hy;
                    float Fhy2 = Fhy * hy;
                    float Fzhy = Fz * hy;
                    Sec   = fmaf(cB, F,    Sec);
                    SesH  = fmaf(sB, Fhy,  SesH);
                    SecH2 = fmaf(cB, Fhy2, SecH2);
                    Sfc   = fmaf(cB, Fz,   Sfc);
                    SfsH  = fmaf(sB, Fzhy, SfsH);
                    Sgc   = fmaf(cB, Fzz,  Sgc);
                    float cBn = cB * cb - sB * sb;
                    sB = sB * cb + cB * sb;
                    cB = cBn;
                }
                float hx  = (float)k0 * K0x;
                float hx2 = hx * hx;
                float cSec = cA * Sec, sSec = sA * Sec;
                Ek  += cSec;
                Gkx = fmaf(-hx, sSec, Gkx);
                Gky = fmaf(-cA, SesH, Gky);
                Gkz = fmaf(cA, Sfc, Gkz);
                Kxx = fmaf(-hx2, cSec, Kxx);
                Kyy = fmaf(-cA, SecH2, Kyy);
                Kxy = fmaf(hx, sA * SesH, Kxy);
                Kxz = fmaf(-hx, sA * Sfc, Kxz);
                Kyz = fmaf(-cA, SfsH, Kyz);
                Kzz = fmaf(cA, Sgc, Kzz);
                float cAn = cA * ca - sA * sa;
                sA = sA * ca + cA * sa;
                cA = cAn;
            }
        } else {
            // generic fallback (never hit on benchmark data)
            #pragma unroll 1
            for (int k0 = r0; k0 < r1; k0++) {
                #pragma unroll 1
                for (int j1 = (k0 == 0 ? 1 : -6); j1 <= 6; j1++) {
                    float fk = (float)k0, fj = (float)j1;
                    float hx = fk * K0x + fj * K1x;
                    float hy = fk * K0y + fj * K1y;
                    float hz = fk * K0z + fj * K1z;
                    float d2 = hx * hx + hy * hy + hz * hz;
                    float dd = sqrtf(d2);
                    float uu = dd * INV2A;
                    float gp = __expf(-uu * uu) * gzp;
                    float x1 = uu + az, x2 = uu - az;
                    float p1 = gp * erfcx_p(fabsf(x1));
                    float p2 = gp * erfcx_p(fabsf(x2));
                    if (aaz > uu) {
                        if (az > 0.f) p2 = 2.f * gp * __expf(x2 * x2) - p2;
                        else          p1 = 2.f * gp * __expf(x1 * x1) - p1;
                    }
                    float s   = p1 + p2;
                    float F   = s * __fdividef(1.f, dd);
                    float Fz  = p1 - p2;
                    float Fzz = fmaf(dd, s, -FOURA_SQPI * gp);
                    float ph2 = fk * alpha + fj * beta;
                    float sT2, cT;
                    sincosf(ph2, &sT2, &cT);
                    float cF = cT * F, sF = sT2 * F, sFz = sT2 * Fz;
                    Ek  += cF;
                    Gkx -= sF * hx;
                    Gky -= sF * hy;
                    Gkz += cT * Fz - sF * hz;
                    Kxx -= cF * hx * hx;
                    Kyy -= cF * hy * hy;
                    Kxy -= cF * hx * hy;
                    Kxz -= cF * hx * hz + sFz * hx;
                    Kyz -= cF * hy * hz + sFz * hy;
                    Kzz += cT * Fzz - cF * hz * hz - 2.f * sFz * hz;
                }
            }
        }

        if (ph == 1) {
            // S2 (z-only); diag z=0 handled naturally
            float erfz = copysignf(1.f - erfcx_p(aaz) * gzp, az);
            Ek  -= dz * erfz + gzp * INV_A_SQPI;
            Gkz -= erfz;
            Kzz -= TWOA_SQPI * gzp;
            // all 9 surviving real-space images (|n|=2 shells are < 4e-17)
            #pragma unroll 1
            for (int im = 0; im < NIMG; im++) {
                float rx = dx + sax[im];
                float ry = dy + say[im];
                float rz = dz + saz[im];
                float dd2 = rx * rx + ry * ry + rz * rz;
                if (dd2 > 0.f && dd2 < (81.0f / (AA * AA))) {
                    float invd  = rsqrtf(dd2);
                    float dr    = dd2 * invd;
                    float ad    = AA * dr;
                    float e     = __expf(-ad * ad);
                    float tt    = erfcx_p(ad) * e;
                    float invd2 = invd * invd;
                    Er += tt * invd;
                    float up  = -(TWOA_SQPI * e + tt * invd) * invd;
                    float upp = TWOA_SQPI * e * (2.f * AA * AA + 2.f * invd2) + 2.f * tt * invd * invd2;
                    float s1v = up * invd;
                    Grx += s1v * rx; Gry += s1v * ry; Grz += s1v * rz;
                    float w = (upp - s1v) * invd2;
                    Rxx += w * rx * rx + s1v;
                    Ryy += w * ry * ry + s1v;
                    Rzz += w * rz * rz + s1v;
                    Rxy += w * rx * ry;
                    Rxz += w * rx * rz;
                    Ryz += w * ry * rz;
                }
            }
        }

        float pk = qq * PK;
        float p3 = qq * (0.5f * KEC);
        float vals[9];
        float E  = pk * Ek + p3 * Er;                // ordered-pair energy partial
        vals[0] = pk * Gkx + p3 * Grx;
        vals[1] = pk * Gky + p3 * Gry;
        vals[2] = pk * Gkz + p3 * Grz;
        vals[3] = pk * Kxx + p3 * Rxx;
        vals[4] = pk * Kyy + p3 * Ryy;
        vals[5] = pk * Kzz + p3 * Rzz;
        vals[6] = pk * Kxy + p3 * Rxy;
        vals[7] = pk * Kxz + p3 * Rxz;
        vals[8] = pk * Kyz + p3 * Ryz;

        int fmj = sfm[j];
        if (fmj >= 0) {
            atomicAdd(&sTm[fmj][0], vals[3]);
            atomicAdd(&sTm[fmj][1], vals[4]);
            atomicAdd(&sTm[fmj][2], vals[5]);
            atomicAdd(&sTm[fmj][3], vals[6]);
            atomicAdd(&sTm[fmj][4], vals[7]);
            atomicAdd(&sTm[fmj][5], vals[8]);
        }

        const unsigned full = 0xffffffffu;
        #pragma unroll
        for (int c = 0; c < 9; c++) {
            float v = vals[c];
            #pragma unroll
            for (int o = 16; o > 0; o >>= 1) v += __shfl_down_sync(full, v, o);
            if ((t & 31) == 0) red2[t >> 5][c] = v;
        }
        float se = blockReduce256(E, red);   // also syncs red2 / sTm
        if (t == 0) atomicAdd(&g_Ec, (double)se);
        if (t < 9) {
            float s = 0.f;
            #pragma unroll
            for (int w = 0; w < 8; w++) s += red2[w][t];
            g_RP[ph][a][t] = s;
        }
        if (t < 24) g_TP[ph][a][t] = sTm[t / 6][t % 6];
    } else {
        // ---- born pairs ----
        int p = (bid - NBLK_PAIR) * 256 + t;
        int i = ii[p], j = jj[p];
        float rx = sRx[j] - sRx[i] + off[p * 3 + 0];
        float ry = sRy[j] - sRy[i] + off[p * 3 + 1];
        float rz = sRz[j] - sRz[i] + off[p * 3 + 2];
        float d2 = rx * rx + ry * ry + rz * rz;
        float d  = sqrtf(d2);
        float H[6] = {0.f, 0.f, 0.f, 0.f, 0.f, 0.f};

        if (d < 6.0f) {
            float n  = n_[p], r0v = r0_[p];
            float qq = fabsf(sq[i] * sq[j]);
            float B  = qq * __powf(r0v, n - 1.f) * __fdividef(1.f, n);
            float dn = __powf(d, -n);
            float cn = __powf(6.0f, -n);
            float y  = B * (dn - cn);
            atomicAdd(&sE[sml[i]], 0.5f * KEC * y);
            float f     = 0.5f * KEC;
            float invd  = __fdividef(1.f, d);
            float invd2 = invd * invd;
            float yp  = -n * B * dn * invd;
            float ypp = n * (n + 1.f) * B * dn * invd2;
            float s1  = f * yp * invd;
            atomicAdd(&g_Gb[j][0],  s1 * rx);
            atomicAdd(&g_Gb[j][1],  s1 * ry);
            atomicAdd(&g_Gb[j][2],  s1 * rz);
            atomicAdd(&g_Gb[i][0], -s1 * rx);
            atomicAdd(&g_Gb[i][1], -s1 * ry);
            atomicAdd(&g_Gb[i][2], -s1 * rz);
            float w = (f * ypp - s1) * invd2;
            H[0] = w * rx * rx + s1; H[1] = w * ry * ry + s1; H[2] = w * rz * rz + s1;
            H[3] = w * rx * ry; H[4] = w * rx * rz; H[5] = w * ry * rz;
        }
        #pragma unroll
        for (int c = 0; c < 6; c++) g_Hb[p][c] = H[c];
        __syncthreads();
        if (t < NMOL) atomicAdd(&g_Eb[t], (double)sE[t]);
    }

    // ---- completion: last block finalizes ----
    __syncthreads();
    if (t == 0) {
        __threadfence();
        int old = atomicAdd(&g_cnt, 1);
        sLast = (old == NBLK - 1) ? 1 : 0;
    }
    __syncthreads();
    if (!sLast) return;
    __threadfence();

    int a2 = t;
    if (a2 < NMOL * 3) sff[a2] = 0.f;
    __syncthreads();

    // aggregate row partials
    float P[9];
    #pragma unroll
    for (int c = 0; c < 9; c++)
        P[c] = g_RP[0][a2][c] + g_RP[1][a2][c];

    float Gx = 8.f * P[0] + g_Gb[a2][0];
    float Gy = 8.f * P[1] + g_Gb[a2][1];
    float Gz = 8.f * P[2] + g_Gb[a2][2];
    g_Gb[a2][0] = 0.f; g_Gb[a2][1] = 0.f; g_Gb[a2][2] = 0.f;   // re-zero for replay
    int m = sfm[a2];
    bool film = (m >= 0);
    if (film) {
        atomicAdd(&sff[m * 3 + 0], -Gx);
        atomicAdd(&sff[m * 3 + 1], -Gy);
        atomicAdd(&sff[m * 3 + 2], -Gz);
    }
    float qa = sq[a2];
    float sq2 = blockReduce256(qa * qa, red);   // syncs publish sff

    float vx = film ? sff[m * 3 + 0] : 0.f;
    float vy = film ? sff[m * 3 + 1] : 0.f;
    float vz = film ? sff[m * 3 + 2] : 0.f;
    sv[a2][0] = vx; sv[a2][1] = vy; sv[a2][2] = vz;

    // coulomb HVP: 8 * (U_a v_a - Sum_m T_am ff_m)
    float Hvx = P[3] * vx + P[6] * vy + P[7] * vz;
    float Hvy = P[6] * vx + P[4] * vy + P[8] * vz;
    float Hvz = P[7] * vx + P[8] * vy + P[5] * vz;
    #pragma unroll
    for (int m2 = 0; m2 < NMOL; m2++) {
        float T0 = g_TP[0][a2][m2 * 6 + 0] + g_TP[1][a2][m2 * 6 + 0];
        float T1 = g_TP[0][a2][m2 * 6 + 1] + g_TP[1][a2][m2 * 6 + 1];
        float T2 = g_TP[0][a2][m2 * 6 + 2] + g_TP[1][a2][m2 * 6 + 2];
        float T3 = g_TP[0][a2][m2 * 6 + 3] + g_TP[1][a2][m2 * 6 + 3];
        float T4 = g_TP[0][a2][m2 * 6 + 4] + g_TP[1][a2][m2 * 6 + 4];
        float T5 = g_TP[0][a2][m2 * 6 + 5] + g_TP[1][a2][m2 * 6 + 5];
        float fx = sff[m2 * 3 + 0], fy = sff[m2 * 3 + 1], fz = sff[m2 * 3 + 2];
        Hvx -= T0 * fx + T3 * fy + T4 * fz;
        Hvy -= T3 * fx + T1 * fy + T5 * fz;
        Hvz -= T4 * fx + T5 * fy + T2 * fz;
    }
    Hvx *= 8.f; Hvy *= 8.f; Hvz *= 8.f;

    float fax[4], fay[4], faz[4];
    #pragma unroll
    for (int k = 0; k < 4; k++) {
        bool me = film && (m == k);
        fax[k] = me ? Hvx : 0.f;
        fay[k] = me ? Hvy : 0.f;
        faz[k] = me ? Hvz : 0.f;
    }
    __syncthreads();   // sv ready

    // born HVP from stored pair hessians
    #pragma unroll 1
    for (int p = a2; p < NPAIRS; p += 256) {
        int i2 = ii[p], j2 = jj[p];
        float h0 = g_Hb[p][0], h1 = g_Hb[p][1], h2 = g_Hb[p][2];
        float h3 = g_Hb[p][3], h4 = g_Hb[p][4], h5 = g_Hb[p][5];
        float dvx = sv[j2][0] - sv[i2][0];
        float dvy = sv[j2][1] - sv[i2][1];
        float dvz = sv[j2][2] - sv[i2][2];
        float wx = h0 * dvx + h3 * dvy + h4 * dvz;
        float wy = h3 * dvx + h1 * dvy + h5 * dvz;
        float wz = h4 * dvx + h5 * dvy + h2 * dvz;
        int mj = sfm[j2], mi = sfm[i2];
        #pragma unroll
        for (int k = 0; k < 4; k++) {
            float s = ((mj == k) ? 1.f : 0.f) - ((mi == k) ? 1.f : 0.f);
            fax[k] = fmaf(s, wx, fax[k]);
            fay[k] = fmaf(s, wy, fay[k]);
            faz[k] = fmaf(s, wz, faz[k]);
        }
    }

    const unsigned full2 = 0xffffffffu;
    #pragma unroll
    for (int k = 0; k < 4; k++) {
        float v0 = fax[k], v1 = fay[k], v2 = faz[k];
        #pragma unroll
        for (int o = 16; o > 0; o >>= 1) {
            v0 += __shfl_down_sync(full2, v0, o);
            v1 += __shfl_down_sync(full2, v1, o);
            v2 += __shfl_down_sync(full2, v2, o);
        }
        if ((t & 31) == 0) {
            red2[t >> 5][k * 3 + 0] = v0;
            red2[t >> 5][k * 3 + 1] = v1;
            red2[t >> 5][k * 3 + 2] = v2;
        }
    }
    __syncthreads();
    if (t < 12) {
        float s = 0.f;
        #pragma unroll
        for (int w = 0; w < 8; w++) s += red2[w][t];
        out[13 + t] = -2.f * s;
    }

    if (t == 0) {
        float yc = (float)g_Ec - sq2 * (AA / SQRTPI_F) * KEC;
        out[4] = yc;
        #pragma unroll
        for (int m2 = 0; m2 < NMOL; m2++) {
            float yb = (float)g_Eb[m2];
            out[m2]     = yc + yb;
            out[5 + m2] = yb;
            float fx = sff[m2 * 3 + 0], fy = sff[m2 * 3 + 1], fz = sff[m2 * 3 + 2];
            out[9 + m2] = fx * fx + fy * fy + fz * fz;
        }
        g_Ec = 0.0;
        g_cnt = 0;
    }
    if (t < NMOL) g_Eb[t] = 0.0;
}

extern "C" void kernel_launch(void* const* d_in, const int* in_sizes, int n_in,
                              void* d_out, int out_size) {
    const float* R      = (const float*)d_in[0];
    const float* shift  = (const float*)d_in[1];
    const float* q      = (const float*)d_in[2];
    const float* off    = (const float*)d_in[3];
    const float* cell   = (const float*)d_in[4];
    const float* recip  = (const float*)d_in[5];
    const float* r0_ij  = (const float*)d_in[6];
    const float* n_ij   = (const float*)d_in[7];
    const int*   idx_i  = (const int*)d_in[8];
    const int*   idx_j  = (const int*)d_in[9];
    const int*   idx_m  = (const int*)d_in[10];
    const int*   isf    = (const int*)d_in[11];
    float* out = (float*)d_out;

    k_all<<<NBLK, 256>>>(R, shift, q, cell, recip, off, r0_ij, n_ij,
                         idx_i, idx_j, idx_m, isf, out);
}